// round 14
// baseline (speedup 1.0000x reference)
#include <cuda_runtime.h>
#include <math.h>
#include <stdint.h>

#define OC    64
#define KDIM  144
#define BFRAG (18*9*64)     // 10368 u32 fragment-major B (incl. ones/pad tile)
#define PLANE 136           // c-plane stride in floats (4 rows x 34)
#define RSTR  34            // slab row stride

// Precomputed (no allocation allowed)
__device__ uint32_t g_wfrag[BFRAG];
__device__ float    g_koff[OC];

// conv smem layout (bytes)
#define KOFF_OFF 0
#define XSUM_OFF 256
#define SDW_OFF  512
#define XS_OFF   1024                        // 16*136*4 = 8704
#define B_OFF    (XS_OFF + 16*PLANE*4)       // 9728
#define SMEM_BYTES (B_OFF + BFRAG*4)         // 51200

__device__ __forceinline__ uint32_t f2tf(float f) {
    uint32_t u;
    asm("cvt.rna.tf32.f32 %0, %1;" : "=r"(u) : "f"(f));
    return u;
}

__device__ __forceinline__ void mma_tf32(float* d, const uint32_t* a, const uint32_t* b) {
    asm volatile(
        "mma.sync.aligned.m16n8k8.row.col.f32.tf32.tf32.f32 "
        "{%0,%1,%2,%3}, {%4,%5,%6,%7}, {%8,%9}, {%0,%1,%2,%3};"
        : "+f"(d[0]), "+f"(d[1]), "+f"(d[2]), "+f"(d[3])
        : "r"(a[0]), "r"(a[1]), "r"(a[2]), "r"(a[3]), "r"(b[0]), "r"(b[1]));
}

// ---------------- prep: fragment-major tf32(exp(k+5)) + koff ----------------
__global__ __launch_bounds__(256)
void prep_kernel(const float* __restrict__ kw_,
                 const float* __restrict__ bias,
                 const float* __restrict__ dxp) {
    const int b = blockIdx.x;
    const int t = threadIdx.x;
    if (b < 36) {
        const int i  = b * 256 + t;        // kf*64 + n
        const int kf = i >> 6, n = i & 63;
        const int idx = ((kf >> 3) * 9 + (n >> 3)) * 64
                      + ((n & 7) * 4 + (kf & 3)) * 2 + ((kf >> 2) & 1);
        g_wfrag[idx] = f2tf(expf(kw_[i] + 5.0f));
    } else {
        for (int i = t; i < 18 * 64; i += 256) {
            const int ks = i >> 6, e = i & 63;
            g_wfrag[(ks * 9 + 8) * 64 + e] = (e < 8) ? 0x3f800000u : 0u;
        }
        __shared__ float part[256];
        const int n = t & 63, q = t >> 6;
        float s = 0.0f;
        #pragma unroll 4
        for (int j = 0; j < 36; j++)
            s += kw_[(q * 36 + j) * OC + n];
        part[t] = s;
        __syncthreads();
        if (t < OC)
            g_koff[t] = bias[t]
                      - dxp[0] * (part[t] + part[t + 64] + part[t + 128] + part[t + 192]);
    }
}

template<int NT0, int NTN>
__device__ __forceinline__ void mma_loop(float (&acc)[3][4],
                                         const uint32_t* p00, const uint32_t* p01,
                                         const uint32_t* p10, const uint32_t* p11,
                                         const uint32_t* __restrict__ smB,
                                         int lane) {
    #pragma unroll
    for (int u = 0; u < 9; u++) {
        const int po = (u / 3) * RSTR + (u % 3);   // compile-time
        #pragma unroll
        for (int e = 0; e < 2; e++) {
            const int ks = 2 * u + e;
            const uint32_t* q0 = e ? p01 : p00;
            const uint32_t* q1 = e ? p11 : p10;
            uint32_t a[4];
            a[0] = q0[po];
            a[1] = q1[po];
            a[2] = q0[po + 4 * PLANE];
            a[3] = q1[po + 4 * PLANE];
            #pragma unroll
            for (int j = 0; j < NTN; j++) {
                const uint2 bv = *(const uint2*)(smB + (ks * 9 + NT0 + j) * 64 + lane * 2);
                uint32_t b[2] = {bv.x, bv.y};
                mma_tf32(acc[j], a, b);
            }
        }
    }
}

__global__ __launch_bounds__(512, 1)
void conv_mma_kernel(const float* __restrict__ x,
                     const float* __restrict__ dwp,
                     float* __restrict__ out) {
    extern __shared__ char sm[];
    float*    koff_s = (float*)(sm + KOFF_OFF);
    float*    xsum_s = (float*)(sm + XSUM_OFF);
    float*    sdw_s  = (float*)(sm + SDW_OFF);
    float*    xs     = (float*)(sm + XS_OFF);    // [16][4][34] padded slab
    uint32_t* smB    = (uint32_t*)(sm + B_OFF);

    const int img = blockIdx.y;
    const int r0  = blockIdx.x * 2;     // output row base (= input row base)
    const int t    = threadIdx.x;
    const int lane = t & 31;
    const int wid  = t >> 5;

    // ---- Copy pre-staged B fragments (vectorized, L2-broadcast) ----
    {
        const uint4* src = (const uint4*)g_wfrag;
        uint4* dst = (uint4*)smB;
        #pragma unroll
        for (int i = t; i < BFRAG / 4; i += 512)
            dst[i] = src[i];
    }
    if (t < OC) koff_s[t] = g_koff[t];
    if (t == 0) sdw_s[0] = dwp[0];

    // ---- Stage x slab: 16ch x 4rows x 32cols, perfectly coalesced float4 ----
    {
        const int c   = t >> 5;          // 0..15
        const int rem = (t & 31) * 4;    // 0..124
        const int row = rem >> 5, col = rem & 31;
        const float4 v = *(const float4*)(x + (size_t)img * 16384 + c * 1024
                                          + (r0 + row) * 32 + col);
        float* d = xs + c * PLANE + row * RSTR + col;
        d[0] = fmaxf(v.x + 5.0f, 1e-12f);
        d[1] = fmaxf(v.y + 5.0f, 1e-12f);
        d[2] = fmaxf(v.z + 5.0f, 1e-12f);
        d[3] = fmaxf(v.w + 5.0f, 1e-12f);
    }
    __syncthreads();

    // ---- MMA: warp = (m-tile wm, n-group wn); A fragments straight from slab ----
    const int wm  = wid & 3;
    const int wn  = wid >> 2;
    const int gr  = lane >> 2;
    const int tig = lane & 3;

    const int m0 = wm * 16 + gr;               // pixel 0..55
    const int m1 = m0 + 8;                     // up to 63 (>=60 dummy)
    const int mm1 = (m1 < 60) ? m1 : 59;
    const uint32_t* b0 = (const uint32_t*)(xs + (m0 / 30) * RSTR + (m0 % 30));
    const uint32_t* b1 = (const uint32_t*)(xs + (mm1 / 30) * RSTR + (mm1 % 30));
    const uint32_t* p00 = b0 + tig * PLANE;
    const uint32_t* p01 = b0 + (8 + tig) * PLANE;
    const uint32_t* p10 = b1 + tig * PLANE;
    const uint32_t* p11 = b1 + (8 + tig) * PLANE;

    float acc[3][4];
    #pragma unroll
    for (int j = 0; j < 3; j++)
        #pragma unroll
        for (int q = 0; q < 4; q++) acc[j][q] = 0.0f;

    if      (wn == 0) mma_loop<0, 3>(acc, p00, p01, p10, p11, smB, lane);
    else if (wn == 1) mma_loop<3, 2>(acc, p00, p01, p10, p11, smB, lane);
    else if (wn == 2) mma_loop<5, 2>(acc, p00, p01, p10, p11, smB, lane);
    else              mma_loop<7, 2>(acc, p00, p01, p10, p11, smB, lane);

    // ---- xsum from ones column (tile 8 = wn3 j=1, local col 0) ----
    if (wn == 3 && tig == 0) {
        xsum_s[m0] = acc[1][0];
        xsum_s[m1] = acc[1][2];
    }
    __syncthreads();

    // ---- Epilogue ----
    const int NTout  = (wn == 0) ? 3 : ((wn == 3) ? 1 : 2);
    const int ntbase = (wn == 0) ? 0 : (2 * wn + 1);
    const float sdw = sdw_s[0];
    #pragma unroll
    for (int h = 0; h < 2; h++) {
        const int m = m0 + h * 8;
        if (m < 60) {
            const int orow = r0 + m / 30, ocol = m % 30;
            const float corr = sdw * (xsum_s[m] - 720.0f);
            float* ob = out + (size_t)img * OC * 900 + orow * 30 + ocol;
            for (int j = 0; j < NTout; j++) {
                const int cb = (ntbase + j) * 8 + 2 * tig;
                ob[(size_t)cb * 900]       = acc[j][h * 2]     - corr + koff_s[cb];
                ob[(size_t)(cb + 1) * 900] = acc[j][h * 2 + 1] - corr + koff_s[cb + 1];
            }
        }
    }
}

extern "C" void kernel_launch(void* const* d_in, const int* in_sizes, int n_in,
                              void* d_out, int out_size) {
    const float* x    = (const float*)d_in[0];
    const float* k    = (const float*)d_in[1];
    const float* bias = (const float*)d_in[2];
    const float* dx   = (const float*)d_in[3];
    const float* dw   = (const float*)d_in[4];
    float* out = (float*)d_out;

    prep_kernel<<<37, 256>>>(k, bias, dx);
    cudaFuncSetAttribute(conv_mma_kernel,
                         cudaFuncAttributeMaxDynamicSharedMemorySize, SMEM_BYTES);
    dim3 grid(15, 8);
    conv_mma_kernel<<<grid, 512, SMEM_BYTES>>>(x, dw, out);
}